// round 17
// baseline (speedup 1.0000x reference)
#include <cuda_runtime.h>
#include <cuda_fp16.h>
#include <mma.h>
#include <math.h>

using namespace nvcuda;

#define Bsz 4
#define Cc 512
#define MID 256
#define CMn 76
#define Hh 128
#define Ww 128
#define HW 16384
#define Pp 1024
#define Np 16

// ---------------- static scratch ----------------
__device__ float  g_pool[Bsz * CMn * Np];
__device__ __half g_smxh[(size_t)64 * 80 * 1024];       // softmax(sim), padded 80 rows
__device__ __half g_localh[(size_t)64 * 80 * 512];      // local (conf folded), padded
__device__ __half g_vvh[76 * 256];                      // v proj (half)
__device__ __half g_xh[(size_t)Bsz * Cc * HW];          // x as half
__device__ __half g_Wq_h[Cc * MID];
__device__ __half g_Wk_h[Cc * MID];
__device__ __half g_Wc_h[MID * Cc];
__device__ __half g_wqk[(size_t)Cc * Cc];               // Wqk = Wq @ Wk^T [ch][ch2]
__device__ float  g_qbk[Cc];                            // Wq @ bk
__device__ float  g_bqwk[Cc];                           // bq @ Wk^T
__device__ float  g_bqbk[1];                            // bq . bk
__device__ __half g_w2[(size_t)64 * 512 * 80];          // W2 per bn [ch][cm]
__device__ float  g_b2[64 * 16 * 80];                   // b2 per bn, replicated 16 rows

// ---------------- cp.async helpers ----------------
__device__ __forceinline__ void cp16(void* dst, const void* src) {
    unsigned d = (unsigned)__cvta_generic_to_shared(dst);
    asm volatile("cp.async.ca.shared.global [%0], [%1], 16;\n" :: "r"(d), "l"(src));
}
__device__ __forceinline__ void cp_commit() { asm volatile("cp.async.commit_group;\n"); }
template <int N>
__device__ __forceinline__ void cp_wait() { asm volatile("cp.async.wait_group %0;\n" :: "n"(N)); }

// convert a 16x16 fp32 warp scratch tile (ld=20) to half and write out (ldg mult of 8).
__device__ __forceinline__ void scr_to_half(const float* scr, __half* gdst, int ldg, int lane) {
    int rr = lane >> 1, c8 = (lane & 1) * 8;
    const float* s = scr + rr * 20 + c8;
    __half2 h0 = __floats2half2_rn(s[0], s[1]);
    __half2 h1 = __floats2half2_rn(s[2], s[3]);
    __half2 h2 = __floats2half2_rn(s[4], s[5]);
    __half2 h3 = __floats2half2_rn(s[6], s[7]);
    uint4 o;
    o.x = *(unsigned*)&h0; o.y = *(unsigned*)&h1;
    o.z = *(unsigned*)&h2; o.w = *(unsigned*)&h3;
    *(uint4*)(gdst + (size_t)rr * ldg + c8) = o;
}

// same, but add addv to every element first
__device__ __forceinline__ void scr_to_half_add(const float* scr, __half* gdst, int ldg,
                                                int lane, const float* addrow) {
    int rr = lane >> 1, c8 = (lane & 1) * 8;
    const float* s = scr + rr * 20 + c8;
    float a = addrow[rr];
    __half2 h0 = __floats2half2_rn(s[0] + a, s[1] + a);
    __half2 h1 = __floats2half2_rn(s[2] + a, s[3] + a);
    __half2 h2 = __floats2half2_rn(s[4] + a, s[5] + a);
    __half2 h3 = __floats2half2_rn(s[6] + a, s[7] + a);
    uint4 o;
    o.x = *(unsigned*)&h0; o.y = *(unsigned*)&h1;
    o.z = *(unsigned*)&h2; o.w = *(unsigned*)&h3;
    *(uint4*)(gdst + (size_t)rr * ldg + c8) = o;
}

// ---------------- 0. merged misc: setup + x->half + pool/softmax + v -------
__global__ void k_misc(const float* __restrict__ x, const float* __restrict__ sim,
                       const float* __restrict__ gcc,
                       const float* __restrict__ Wq, const float* __restrict__ Wk,
                       const float* __restrict__ Wc,
                       const float* __restrict__ Wv, const float* __restrict__ bv,
                       float* __restrict__ out_tail) {
    __shared__ float red[256];
    __shared__ float sg[512];
    int blk = blockIdx.x;
    int t = threadIdx.x;

    if (blk < 256) {
        int g = blk * 256 + t;
        int stride = 256 * 256;
        for (int i = g; i < Cc * MID; i += stride) {
            g_Wq_h[i] = __float2half(Wq[i]);
            g_Wk_h[i] = __float2half(Wk[i]);
            g_Wc_h[i] = __float2half(Wc[i]);
        }
        for (int i = g; i < 64 * 4 * 1024; i += stride) {
            int bn = i >> 12, rem = i & 4095;
            g_smxh[((size_t)bn * 80 + 76) * 1024 + rem] = __float2half(0.f);
        }
        for (int i = g; i < 64 * 4 * 512; i += stride) {
            int bn = i >> 11, rem = i & 2047;
            g_localh[((size_t)bn * 80 + 76) * 512 + rem] = __float2half(0.f);
        }
    } else if (blk < 2304) {
        size_t n8 = (size_t)Bsz * Cc * HW / 8;
        size_t g = (size_t)(blk - 256) * 256 + t;
        size_t stride = (size_t)2048 * 256;
        for (; g < n8; g += stride) {
            const float4* s = (const float4*)x + g * 2;
            float4 a = s[0], b = s[1];
            __half2 h0 = __floats2half2_rn(a.x, a.y);
            __half2 h1 = __floats2half2_rn(a.z, a.w);
            __half2 h2 = __floats2half2_rn(b.x, b.y);
            __half2 h3 = __floats2half2_rn(b.z, b.w);
            uint4 o;
            o.x = *(unsigned*)&h0; o.y = *(unsigned*)&h1;
            o.z = *(unsigned*)&h2; o.w = *(unsigned*)&h3;
            ((uint4*)g_xh)[g] = o;
        }
    } else if (blk < 7168) {
        int id = blk - 2304;
        int cm = id % CMn;
        int bn = id / CMn;
        int n = bn & 15, b = bn >> 4;
        int i0 = (n >> 2) * 32, j0 = (n & 3) * 32;
        const float* base = sim + ((size_t)b * CMn + cm) * HW;
        float v[4];
        float mx = -1e30f, sraw = 0.f;
#pragma unroll
        for (int it = 0; it < 4; it++) {
            int p = t + it * 256;
            int pi = p >> 5, pj = p & 31;
            v[it] = base[(i0 + pi) * Ww + j0 + pj];
            mx = fmaxf(mx, v[it]);
            sraw += v[it];
        }
        red[t] = sraw; __syncthreads();
        for (int o = 128; o > 0; o >>= 1) {
            if (t < o) red[t] += red[t + o];
            __syncthreads();
        }
        if (t == 0) {
            float m = red[0] * (1.0f / 1024.0f);
            int pid = (b * CMn + cm) * 16 + n;
            g_pool[pid] = m;
            out_tail[pid] = m;
        }
        __syncthreads();
        red[t] = mx; __syncthreads();
        for (int o = 128; o > 0; o >>= 1) {
            if (t < o) red[t] = fmaxf(red[t], red[t + o]);
            __syncthreads();
        }
        float gmx = red[0]; __syncthreads();
        float s = 0.f;
#pragma unroll
        for (int it = 0; it < 4; it++) { v[it] = expf(v[it] - gmx); s += v[it]; }
        red[t] = s; __syncthreads();
        for (int o = 128; o > 0; o >>= 1) {
            if (t < o) red[t] += red[t + o];
            __syncthreads();
        }
        float inv = 1.0f / red[0];
        __half* dst = g_smxh + ((size_t)bn * 80 + cm) * Pp;
#pragma unroll
        for (int it = 0; it < 4; it++) { int p = t + it * 256; dst[p] = __float2half(v[it] * inv); }
    } else {
        int c = blk - 7168;
        for (int k = t; k < 512; k += 256) sg[k] = gcc[c * 512 + k];
        __syncthreads();
        float acc = 0.f;
        for (int k = 0; k < 512; k++) acc += sg[k] * Wv[k * MID + t];
        g_vvh[c * MID + t] = __float2half(acc + bv[t]);
    }
}

// ---------------- 1. Wqk = Wq @ Wk^T [512x512] + qbk/bqWk/bqbk -------------
// grid 17: blocks 0..15 = 128x128 WMMA tiles (direct-from-global, L2-resident);
// block 16 = vectors.
__global__ __launch_bounds__(256) void k_wqk(const float* __restrict__ bq,
                                             const float* __restrict__ bk) {
    __shared__ __align__(16) float scr[8][16][20];
    int blk = blockIdx.x;
    int tid = threadIdx.x;
    int lane = tid & 31;
    int wid = tid >> 5;

    if (blk < 16) {
        int i0 = (blk >> 2) * 128, j0 = (blk & 3) * 128;
        int qm = wid & 1;          // 2 warps over 128 rows (64 each)
        int qn = wid >> 1;         // 4 warps over 128 cols (32 each)
        wmma::fragment<wmma::accumulator, 16, 16, 16, float> acc[4][2];
#pragma unroll
        for (int i = 0; i < 4; i++)
#pragma unroll
            for (int j = 0; j < 2; j++) wmma::fill_fragment(acc[i][j], 0.f);
        for (int k0 = 0; k0 < 256; k0 += 16) {
            wmma::fragment<wmma::matrix_a, 16, 16, 16, __half, wmma::row_major> af[4];
            wmma::fragment<wmma::matrix_b, 16, 16, 16, __half, wmma::col_major> bf[2];
#pragma unroll
            for (int i = 0; i < 4; i++)
                wmma::load_matrix_sync(af[i],
                    g_Wq_h + (size_t)(i0 + qm * 64 + i * 16) * 256 + k0, 256);
#pragma unroll
            for (int j = 0; j < 2; j++)
                wmma::load_matrix_sync(bf[j],
                    g_Wk_h + (size_t)(j0 + qn * 32 + j * 16) * 256 + k0, 256);
#pragma unroll
            for (int i = 0; i < 4; i++)
#pragma unroll
                for (int j = 0; j < 2; j++)
                    wmma::mma_sync(acc[i][j], af[i], bf[j], acc[i][j]);
        }
#pragma unroll
        for (int i = 0; i < 4; i++)
#pragma unroll
            for (int j = 0; j < 2; j++) {
                wmma::store_matrix_sync(&scr[wid][0][0], acc[i][j], 20, wmma::mem_row_major);
                __syncwarp();
                scr_to_half(&scr[wid][0][0],
                            g_wqk + (size_t)(i0 + qm * 64 + i * 16) * 512 + j0 + qn * 32 + j * 16,
                            512, lane);
                __syncwarp();
            }
    } else {
        for (int ch = tid; ch < 512; ch += 256) {
            float s = 0.f;
            for (int mid = 0; mid < 256; mid++)
                s += __half2float(g_Wq_h[(size_t)ch * 256 + mid]) * bk[mid];
            g_qbk[ch] = s;
        }
        for (int c2 = tid; c2 < 512; c2 += 256) {
            float s = 0.f;
            for (int mid = 0; mid < 256; mid++)
                s += bq[mid] * __half2float(g_Wk_h[(size_t)c2 * 256 + mid]);
            g_bqwk[c2] = s;
        }
        if (tid == 0) {
            float s = 0.f;
            for (int mid = 0; mid < 256; mid++) s += bq[mid] * bk[mid];
            g_bqbk[0] = s;
        }
    }
}

// ---------------- 3. local = smx^T @ xs * conf  (WMMA, cp.async x2) --------
__device__ __forceinline__ void local_stage(int tid, __half* Adst, __half* Bdst,
                                            const __half* Asrc, const __half* Bsrc,
                                            int it, int nBase, int baseoff) {
    for (int idx = tid; idx < 832; idx += 320) {
        if (idx < 320) {
            int row = idx >> 2, col = (idx & 3) * 8;
            cp16(Adst + row * 40 + col, Asrc + (size_t)row * 1024 + it * 32 + col);
        } else {
            int j = idx - 320;
            int row = j >> 2, col = (j & 3) * 8;
            cp16(Bdst + row * 40 + col,
                 Bsrc + (size_t)(nBase + row) * HW + baseoff + it * Ww + col);
        }
    }
    cp_commit();
}

__global__ __launch_bounds__(320, 2) void k_local_w() {
    __shared__ __align__(16) union {
        struct { __half A[2][80][40]; __half B[2][128][40]; } s;
        float C[80 * 136];
    } u;
    int bn = blockIdx.y;
    int b = bn >> 4, np = bn & 15;
    int i0 = (np >> 2) * 32, j0 = (np & 3) * 32;
    int baseoff = i0 * Ww + j0;
    int nBase = blockIdx.x * 128;
    const __half* Asrc = g_smxh + (size_t)bn * 80 * 1024;
    const __half* Bsrc = g_xh + (size_t)b * Cc * HW;
    int tid = threadIdx.x;
    int wid = tid >> 5;
    int wm = wid % 5, wn = wid / 5;

    wmma::fragment<wmma::accumulator, 16, 16, 16, float> c[4];
#pragma unroll
    for (int j = 0; j < 4; j++) wmma::fill_fragment(c[j], 0.f);

    local_stage(tid, &u.s.A[0][0][0], &u.s.B[0][0][0], Asrc, Bsrc, 0, nBase, baseoff);
    for (int it = 0; it < 32; it++) {
        if (it + 1 < 32) {
            int s2 = (it + 1) & 1;
            local_stage(tid, &u.s.A[s2][0][0], &u.s.B[s2][0][0], Asrc, Bsrc, it + 1, nBase, baseoff);
            cp_wait<1>();
        } else {
            cp_wait<0>();
        }
        __syncthreads();
        int s = it & 1;
#pragma unroll
        for (int ks = 0; ks < 32; ks += 16) {
            wmma::fragment<wmma::matrix_a, 16, 16, 16, __half, wmma::row_major> af;
            wmma::load_matrix_sync(af, &u.s.A[s][wm * 16][ks], 40);
#pragma unroll
            for (int j = 0; j < 4; j++) {
                wmma::fragment<wmma::matrix_b, 16, 16, 16, __half, wmma::col_major> bf;
                wmma::load_matrix_sync(bf, &u.s.B[s][wn * 64 + j * 16][ks], 40);
                wmma::mma_sync(c[j], af, bf, c[j]);
            }
        }
        __syncthreads();
    }
#pragma unroll
    for (int j = 0; j < 4; j++)
        wmma::store_matrix_sync(&u.C[(wm * 16) * 136 + wn * 64 + j * 16], c[j], 136,
                                wmma::mem_row_major);
    __syncthreads();
    for (int idx = tid; idx < 76 * 128; idx += 320) {
        int cc = idx >> 7, nn = idx & 127;
        float conf = g_pool[(b * CMn + cc) * 16 + np];
        g_localh[((size_t)bn * 80 + cc) * 512 + nBase + nn] =
            __float2half(u.C[cc * 136 + nn] * conf);
    }
}

// ---------------- 5. W2 = Wqk @ local^T + qbk; b2 = bqWk @ local^T + bqbk --
// grid (4 mchunks, 64 bn), 256 threads (8 warps).
// smem: dbuf 2 x { A[128][72]h 18432 + L[80][72]h 11520 } = 59904 | bqwk f 2048
#define W2_SMEM 61952

__global__ __launch_bounds__(256) void k_w2() {
    extern __shared__ __align__(16) char dynw[];
    float* bqwk_s = (float*)(dynw + 59904);
    int m0 = blockIdx.x * 128;
    int bn = blockIdx.y;
    int tid = threadIdx.x;
    int lane = tid & 31;
    int wid = tid >> 5;
    const __half* Lsrc = g_localh + (size_t)bn * 80 * 512;

    for (int i = tid; i < 512; i += 256) bqwk_s[i] = g_bqwk[i];

    auto stage = [&](int s, int k0) {
        char* base = dynw + s * 29952;
        for (int idx = tid; idx < 1664; idx += 256) {
            if (idx < 1024) {
                int r = idx >> 3, c8 = (idx & 7) * 8;
                cp16((__half*)base + r * 72 + c8, g_wqk + (size_t)(m0 + r) * 512 + k0 + c8);
            } else {
                int j = idx - 1024;
                int r = j >> 3, c8 = (j & 7) * 8;
                cp16((__half*)(base + 18432) + r * 72 + c8, Lsrc + (size_t)r * 512 + k0 + c8);
            }
        }
        cp_commit();
    };

    wmma::fragment<wmma::accumulator, 16, 16, 16, float> acc[5];
#pragma unroll
    for (int f = 0; f < 5; f++) wmma::fill_fragment(acc[f], 0.f);
    float b2acc = 0.f;

    stage(0, 0);
    for (int it = 0; it < 8; it++) {
        if (it + 1 < 8) {
            stage((it + 1) & 1, (it + 1) * 64);
            cp_wait<1>();
        } else {
            cp_wait<0>();
        }
        __syncthreads();
        int s = it & 1;
        __half* As = (__half*)(dynw + s * 29952);
        __half* Ls = (__half*)(dynw + s * 29952 + 18432);
#pragma unroll
        for (int ks = 0; ks < 64; ks += 16) {
            wmma::fragment<wmma::matrix_a, 16, 16, 16, __half, wmma::row_major> af;
            wmma::load_matrix_sync(af, As + (wid * 16) * 72 + ks, 72);
#pragma unroll
            for (int f = 0; f < 5; f++) {
                wmma::fragment<wmma::matrix_b, 16, 16, 16, __half, wmma::col_major> bf;
                wmma::load_matrix_sync(bf, Ls + (f * 16) * 72 + ks, 72);
                wmma::mma_sync(acc[f], af, bf, acc[f]);
            }
        }
        if (blockIdx.x == 0 && tid < 80) {
            const __half* lrow = Ls + tid * 72;
            const float* bw = bqwk_s + it * 64;
#pragma unroll 16
            for (int k = 0; k < 64; k++) b2acc += __half2float(lrow[k]) * bw[k];
        }
        __syncthreads();
    }
    if (blockIdx.x == 0 && tid < 80) {
        float v = b2acc + g_bqbk[0];
        for (int r = 0; r < 16; r++) g_b2[(size_t)bn * 1280 + r * 80 + tid] = v;
    }
    float* scr = (float*)dynw + wid * 320;
#pragma unroll
    for (int f = 0; f < 5; f++) {
        wmma::store_matrix_sync(scr, acc[f], 20, wmma::mem_row_major);
        __syncwarp();
        scr_to_half_add(scr, g_w2 + ((size_t)bn * 512 + m0 + wid * 16) * 80 + f * 16, 80,
                        lane, g_qbk + m0 + wid * 16);
        __syncwarp();
    }
}

// ---------------- 7. fused attention + conv: S, softmax, PV, O@Wc+BN+ReLU --
#define ATT3_SMEM 81920

__global__ __launch_bounds__(256) void k_attq(const float* __restrict__ gamma,
                                              const float* __restrict__ beta,
                                              const float* __restrict__ mean,
                                              const float* __restrict__ var,
                                              float* __restrict__ y) {
    extern __shared__ __align__(16) char dyn[];
    __half* P  = (__half*)dyn;                      // [64][88]
    float*  Sf = (float*)(dyn + 11264);             // [64][92]
    __half* Osm = (__half*)(dyn + 11264);           // [64][264]
    int bn = blockIdx.y;
    int b = bn >> 4, np = bn & 15;
    int i0 = (np >> 2) * 32, j0 = (np & 3) * 32;
    int mBase = blockIdx.x * 64;
    int tid = threadIdx.x;
    int lane = tid & 31;
    int wid = tid >> 5;
    int wm = wid & 3;
    int wn = wid >> 2;
    const __half* xb = g_xh + (size_t)b * Cc * HW;
    const __half* w2 = g_w2 + (size_t)bn * 512 * 80;
    int nfr = (wn == 0) ? 3 : 2;
    int nb0 = (wn == 0) ? 0 : 48;

    // ===== phase S: S[64px][80cm] = x^T @ W2 + b2 =====
    {
        wmma::fragment<wmma::accumulator, 16, 16, 16, float> sacc[3];
        for (int f = 0; f < nfr; f++)
            wmma::load_matrix_sync(sacc[f], g_b2 + (size_t)bn * 1280 + nb0 + f * 16, 80,
                                   wmma::mem_row_major);

        auto stage = [&](int s, int k0) {
            char* base = dyn + 45056 + s * 10240;
            for (int idx = tid; idx < 576; idx += 256) {
                if (idx < 256) {
                    int ch = idx >> 3;
                    int px = (idx & 7) * 8;
                    int p = mBase + px;
                    cp16((__half*)base + ch * 72 + px,
                         xb + (size_t)(k0 + ch) * HW + (i0 + (p >> 5)) * 128 + j0 + (p & 31));
                } else {
                    int j = idx - 256;
                    int kk = j / 10;
                    int n = (j % 10) * 8;
                    cp16((__half*)(base + 4608) + kk * 88 + n,
                         w2 + (size_t)(k0 + kk) * 80 + n);
                }
            }
            cp_commit();
        };

        stage(0, 0);
        for (int it = 0; it < 16; it++) {
            if (it + 1 < 16) {
                stage((it + 1) & 1, (it + 1) * 32);
                cp_wait<1>();
            } else {
                cp_wait<0>();
            }
            __syncthreads();
            int s = it & 1;
            __half* As = (__half*)(dyn + 45056 + s * 10240);
            __half* Bs = (__half*)(dyn + 45056 + s * 10240 + 4608);
#pragma unroll
            for (int ks = 0; ks < 32; ks += 16) {
                wmma::fragment<wmma::matrix_a, 16, 16, 16, __half, wmma::col_major> af;
                wmma::load_matrix_sync(af, As + ks * 72 + wm * 16, 72);
                for (int f = 0; f < nfr; f++) {
                    wmma::fragment<wmma::matrix_b, 16, 16, 16, __half, wmma::row_major> bf;
                    wmma::load_matrix_sync(bf, Bs + ks * 88 + nb0 + f * 16, 88);
                    wmma::mma_sync(sacc[f], af, bf, sacc[f]);
                }
            }
            __syncthreads();
        }
        for (int f = 0; f < nfr; f++)
            wmma::store_matrix_sync(Sf + (wm * 16) * 92 + nb0 + f * 16, sacc[f], 92,
                                    wmma::mem_row_major);
    }
    __syncthreads();

    // ===== softmax -> P =====
    if (tid < 64) {
        const float* srow = Sf + tid * 92;
        float mx = -1e30f;
        for (int c = 0; c < 76; c++) mx = fmaxf(mx, srow[c]);
        float s = 0.f;
        float e[76];
        for (int c = 0; c < 76; c++) { e[c] = expf(srow[c] - mx); s += e[c]; }
        float inv = 1.0f / s;
        __half* prow = P + tid * 88;
        for (int c = 0; c < 76; c++) prow[c] = __float2half(e[c] * inv);
        prow[76] = __float2half(0.f);
        prow[77] = __float2half(0.f);
        prow[78] = __float2half(0.f);
        prow[79] = __float2half(0.f);
    }
    __syncthreads();

    // ===== phase PV: O = P @ V -> Osm (half) =====
    {
        __half* Vsm = (__half*)(dyn + 45056);            // [80][136]
        float* scr2 = (float*)(dyn + 45056 + 21760) + wid * 320;
        for (int hb = 0; hb < 2; hb++) {
            for (int idx = tid; idx < 1280; idx += 256) {
                int row = idx >> 4, c8 = (idx & 15) * 8;
                uint4 z = {0, 0, 0, 0};
                uint4 val = (row < 76) ? *(const uint4*)&g_vvh[row * 256 + hb * 128 + c8] : z;
                *(uint4*)(Vsm + row * 136 + c8) = val;
            }
            __syncthreads();
            wmma::fragment<wmma::accumulator, 16, 16, 16, float> oacc[4];
#pragma unroll
            for (int j = 0; j < 4; j++) wmma::fill_fragment(oacc[j], 0.f);
#pragma unroll
            for (int kc = 0; kc < 5; kc++) {
                int ks = kc * 16;
                wmma::fragment<wmma::matrix_a, 16, 16, 16, __half, wmma::row_major> pf;
                wmma::load_matrix_sync(pf, P + (wm * 16) * 88 + ks, 88);
#pragma unroll
                for (int j = 0; j < 4; j++) {
                    wmma::fragment<wmma::matrix_b, 16, 16, 16, __half, wmma::row_major> vf;
                    wmma::load_matrix_sync(vf, Vsm + ks * 136 + wn * 64 + j * 16, 136);
                    wmma::mma_sync(oacc[j], pf, vf, oacc[j]);
                }
            }
            __half* obase = Osm + (wm * 16) * 264 + hb * 128 + wn * 64;
#pragma unroll
            for (int j = 0; j < 4; j++) {
                wmma::store_matrix_sync(scr2, oacc[j], 20, wmma::mem_row_major);
                __syncwarp();
                scr_to_half(scr2, obase + j * 16, 264, lane);
                __syncwarp();
            }
            __syncthreads();
        }
    }

    // ===== phase C: y = ReLU(BN(O @ Wc)), 4 chunks x 128 ch, K-chunk 64 =====
    // warp decode 2M x 4N: warp tile 32px x 32ch
    int cm2 = wid & 1;
    int cn4 = wid >> 1;
    for (int nc = 0; nc < 4; nc++) {
        int nb = nc * 128;
        wmma::fragment<wmma::accumulator, 16, 16, 16, float> cacc[2][2];
#pragma unroll
        for (int i = 0; i < 2; i++)
#pragma unroll
            for (int j = 0; j < 2; j++) wmma::fill_fragment(cacc[i][j], 0.f);

        auto stageC = [&](int s, int k0) {
            __half* Bs = (__half*)(dyn + 45056 + s * 17408);
#pragma unroll
            for (int l = 0; l < 4; l++) {
                int idx = tid + l * 256;
                int kk = idx >> 4, c8 = (idx & 15) * 8;
                cp16(Bs + kk * 136 + c8, g_Wc_h + (size_t)(k0 + kk) * Cc + nb + c8);
            }
            cp_commit();
        };
        stageC(0, 0);
        for (int it = 0; it < 4; it++) {
            if (it + 1 < 4) {
                stageC((it + 1) & 1, (it + 1) * 64);
                cp_wait<1>();
            } else {
                cp_wait<0>();
            }
            __syncthreads();
            int s = it & 1;
            __half* Bs = (__half*)(dyn + 45056 + s * 17408);
            int k0 = it * 64;
#pragma unroll
            for (int ks = 0; ks < 64; ks += 16) {
                wmma::fragment<wmma::matrix_a, 16, 16, 16, __half, wmma::row_major> af[2];
                wmma::fragment<wmma::matrix_b, 16, 16, 16, __half, wmma::row_major> bf[2];
#pragma unroll
                for (int i = 0; i < 2; i++)
                    wmma::load_matrix_sync(af[i], Osm + (cm2 * 32 + i * 16) * 264 + k0 + ks, 264);
#pragma unroll
                for (int j = 0; j < 2; j++)
                    wmma::load_matrix_sync(bf[j], Bs + ks * 136 + cn4 * 32 + j * 16, 136);
#pragma unroll
                for (int i = 0; i < 2; i++)
#pragma unroll
                    for (int j = 0; j < 2; j++)
                        wmma::mma_sync(cacc[i][j], af[i], bf[j], cacc[i][j]);
            }
            __syncthreads();
        }
        float* Cout = (float*)(dyn + 45056);
#pragma unroll
        for (int i = 0; i < 2; i++)
#pragma unroll
            for (int j = 0; j < 2; j++)
                wmma::store_matrix_sync(Cout + (cn4 * 32 + j * 16) * 72 + cm2 * 32 + i * 16,
                                        cacc[i][j], 72, wmma::mem_col_major);
        __syncthreads();
        {
            int chl = tid >> 1;
            int half = tid & 1;
            int ch = nb + chl;
            float iv = gamma[ch] / sqrtf(var[ch] + 1e-5f);
            float ad = beta[ch] - mean[ch] * iv;
            int px0 = half * 32;
            int p = mBase + px0;
            float* ydst = y + ((size_t)b * Cc + ch) * HW + (i0 + (p >> 5)) * 128 + j0;
            const float* crow = Cout + chl * 72 + px0;
#pragma unroll
            for (int l = 0; l < 8; l++) {
                float4 v = *(const float4*)&crow[l * 4];
                v.x = fmaxf(v.x * iv + ad, 0.f);
                v.y = fmaxf(v.y * iv + ad, 0.f);
                v.z = fmaxf(v.z * iv + ad, 0.f);
                v.w = fmaxf(v.w * iv + ad, 0.f);
                *(float4*)&ydst[l * 4] = v;
            }
        }
        __syncthreads();
    }
}

// ---------------- launcher ----------------
extern "C" void kernel_launch(void* const* d_in, const int* in_sizes, int n_in,
                              void* d_out, int out_size) {
    const float* x   = (const float*)d_in[0];
    const float* sim = (const float*)d_in[1];
    const float* gcc = (const float*)d_in[2];
    const float* Wq  = (const float*)d_in[3];
    const float* bq  = (const float*)d_in[4];
    const float* Wk  = (const float*)d_in[5];
    const float* bk  = (const float*)d_in[6];
    const float* Wv  = (const float*)d_in[7];
    const float* bv  = (const float*)d_in[8];
    const float* Wc  = (const float*)d_in[9];
    const float* gm  = (const float*)d_in[10];
    const float* bt  = (const float*)d_in[11];
    const float* mn  = (const float*)d_in[12];
    const float* vr  = (const float*)d_in[13];
    float* y = (float*)d_out;
    float* tail = y + (size_t)Bsz * Cc * HW;

    cudaFuncSetAttribute(k_w2, cudaFuncAttributeMaxDynamicSharedMemorySize, W2_SMEM);
    cudaFuncSetAttribute(k_attq, cudaFuncAttributeMaxDynamicSharedMemorySize, ATT3_SMEM);

    k_misc<<<7244, 256>>>(x, sim, gcc, Wq, Wk, Wc, Wv, bv, tail);
    k_wqk<<<17, 256>>>(bq, bk);
    k_local_w<<<dim3(4, 64), 320>>>();
    k_w2<<<dim3(4, 64), 256, W2_SMEM>>>();
    k_attq<<<dim3(16, 64), 256, ATT3_SMEM>>>(gm, bt, mn, vr, y);
}